// round 1
// baseline (speedup 1.0000x reference)
#include <cuda_runtime.h>
#include <cuda_bf16.h>
#include <cstdint>

// Problem constants
#define NN 50000
#define EE 800000
#define FF 128
#define HH 8
#define DD 16
// logits = (clip(a) + bias) / SCALING, SCALING = D^-0.5 = 0.25  => *4

// ---------------- device scratch (static, no runtime alloc) ----------------
__device__ float g_q[(size_t)NN * FF];
__device__ float g_k[(size_t)NN * FF];
__device__ float g_v[(size_t)NN * FF];
__device__ float g_logits[(size_t)EE * HH];   // later overwritten with exp()
__device__ float g_gates[(size_t)EE * HH];
__device__ unsigned g_m[(size_t)NN * HH];     // monotone-mapped float max
__device__ float g_s[(size_t)NN * HH];
__device__ float g_agg[(size_t)NN * FF];

// monotone float <-> uint mapping (order preserving for all reals)
__device__ __forceinline__ unsigned fmap(float f) {
    unsigned u = __float_as_uint(f);
    return (u & 0x80000000u) ? ~u : (u | 0x80000000u);
}
__device__ __forceinline__ float funmap(unsigned u) {
    u = (u & 0x80000000u) ? (u & 0x7FFFFFFFu) : ~u;
    return __uint_as_float(u);
}

// ---------------- kernel 0: zero init ----------------
__global__ void zero_kernel() {
    int stride = gridDim.x * blockDim.x;
    int i = blockIdx.x * blockDim.x + threadIdx.x;
    for (int j = i; j < NN * FF; j += stride) g_agg[j] = 0.0f;
    for (int j = i; j < NN * HH; j += stride) { g_m[j] = 0u; g_s[j] = 0.0f; }
}

// ---------------- kernel 1/5: C[M,128] = A[M,128] @ W^T (W [128,128]) ------
// BM=128, BN=128(full), BK=8. 256 threads, each computes 8x8.
__global__ void __launch_bounds__(256, 2)
gemm128_xWt(const float* __restrict__ A, const float* __restrict__ W,
            float* __restrict__ C, int M) {
    __shared__ float As[8][128];   // As[k][m]
    __shared__ float Bs[8][128];   // Bs[k][n] = W[n][k]
    const int block_m = blockIdx.x * 128;
    const int tid = threadIdx.x;
    const int trow = tid / 16;     // 0..15
    const int tcol = tid % 16;     // 0..15

    const int lr  = tid >> 1;          // 0..127 : row within tile / W row n
    const int lc4 = (tid & 1) * 4;     // 0 or 4
    const bool a_valid = (block_m + lr) < M;

    float acc[8][8];
#pragma unroll
    for (int i = 0; i < 8; i++)
#pragma unroll
        for (int j = 0; j < 8; j++) acc[i][j] = 0.0f;

    for (int k0 = 0; k0 < 128; k0 += 8) {
        float4 a4 = make_float4(0.f, 0.f, 0.f, 0.f);
        if (a_valid)
            a4 = *(const float4*)&A[(size_t)(block_m + lr) * 128 + k0 + lc4];
        float4 b4 = *(const float4*)&W[(size_t)lr * 128 + k0 + lc4];
        As[lc4 + 0][lr] = a4.x; As[lc4 + 1][lr] = a4.y;
        As[lc4 + 2][lr] = a4.z; As[lc4 + 3][lr] = a4.w;
        Bs[lc4 + 0][lr] = b4.x; Bs[lc4 + 1][lr] = b4.y;
        Bs[lc4 + 2][lr] = b4.z; Bs[lc4 + 3][lr] = b4.w;
        __syncthreads();
#pragma unroll
        for (int k = 0; k < 8; k++) {
            float af[8], bf[8];
            *(float4*)&af[0] = *(const float4*)&As[k][trow * 8 + 0];
            *(float4*)&af[4] = *(const float4*)&As[k][trow * 8 + 4];
            *(float4*)&bf[0] = *(const float4*)&Bs[k][tcol * 8 + 0];
            *(float4*)&bf[4] = *(const float4*)&Bs[k][tcol * 8 + 4];
#pragma unroll
            for (int i = 0; i < 8; i++)
#pragma unroll
                for (int j = 0; j < 8; j++) acc[i][j] += af[i] * bf[j];
        }
        __syncthreads();
    }
#pragma unroll
    for (int i = 0; i < 8; i++) {
        int m = block_m + trow * 8 + i;
        if (m < M) {
            *(float4*)&C[(size_t)m * 128 + tcol * 8 + 0] =
                make_float4(acc[i][0], acc[i][1], acc[i][2], acc[i][3]);
            *(float4*)&C[(size_t)m * 128 + tcol * 8 + 4] =
                make_float4(acc[i][4], acc[i][5], acc[i][6], acc[i][7]);
        }
    }
}

// ---------------- kernel 2: per-edge logits, gates, segment max ------------
// 256 threads = 32 edges x 8 heads per block. grid = EE/32 blocks.
__global__ void __launch_bounds__(256)
edge_logits_kernel(const float* __restrict__ ef,
                   const float* __restrict__ Wedge,
                   const float* __restrict__ Wgate,
                   const int* __restrict__ src,
                   const int* __restrict__ dst) {
    __shared__ float We[HH][FF + 4];
    __shared__ float Wg[HH][FF + 4];
    const int tid = threadIdx.x;
    {
        int h = tid >> 5;            // 0..7
        int c = (tid & 31) * 4;      // 0..124
        *(float4*)&We[h][c] = *(const float4*)&Wedge[h * FF + c];
        *(float4*)&Wg[h][c] = *(const float4*)&Wgate[h * FF + c];
    }
    __syncthreads();

    const int e = blockIdx.x * 32 + (tid >> 3);
    const int h = tid & 7;
    const int sn = src[e];
    const int dn = dst[e];

    // q[src] . k[dst] for this head (16 elems)
    const float4* qrow = (const float4*)&g_q[(size_t)sn * FF + h * DD];
    const float4* krow = (const float4*)&g_k[(size_t)dn * FF + h * DD];
    float a = 0.0f;
#pragma unroll
    for (int j = 0; j < 4; j++) {
        float4 q4 = qrow[j], k4 = krow[j];
        a += q4.x * k4.x + q4.y * k4.y + q4.z * k4.z + q4.w * k4.w;
    }

    // edge_feat projections (bias & gate) — ef broadcast across 8 head-threads
    const float4* efrow = (const float4*)&ef[(size_t)e * FF];
    float bias = 0.0f, gdot = 0.0f;
#pragma unroll
    for (int k4 = 0; k4 < 32; k4++) {
        float4 e4 = efrow[k4];
        float4 w4 = *(const float4*)&We[h][k4 * 4];
        float4 g4 = *(const float4*)&Wg[h][k4 * 4];
        bias += e4.x * w4.x + e4.y * w4.y + e4.z * w4.z + e4.w * w4.w;
        gdot += e4.x * g4.x + e4.y * g4.y + e4.z * g4.z + e4.w * g4.w;
    }

    float logit = (fminf(fmaxf(a, -5.0f), 5.0f) + bias) * 4.0f;
    float gate  = 1.0f / (1.0f + expf(-gdot));
    int idx = e * HH + h;
    g_logits[idx] = logit;
    g_gates[idx]  = gate;
    atomicMax(&g_m[dn * HH + h], fmap(logit));
}

// ---------------- kernel 3: exp(logit - m[dst]) and segment sum ------------
__global__ void __launch_bounds__(256)
edge_exp_kernel(const int* __restrict__ dst) {
    int i = blockIdx.x * blockDim.x + threadIdx.x;   // < EE*HH, exact grid
    int e = i >> 3, h = i & 7;
    int d = dst[e];
    float mf = funmap(g_m[d * HH + h]);
    float ex = expf(g_logits[i] - mf);
    g_logits[i] = ex;
    atomicAdd(&g_s[d * HH + h], ex);
}

// ---------------- kernel 4: weighted scatter-aggregate ---------------------
// warp per edge; lane l handles elems 4l..4l+3 (head = l>>2). v4 RED to agg.
__global__ void __launch_bounds__(256)
edge_scatter_kernel(const int* __restrict__ src, const int* __restrict__ dst) {
    int e = (blockIdx.x * blockDim.x + threadIdx.x) >> 5;
    if (e >= EE) return;
    int lane = threadIdx.x & 31;
    int h = lane >> 2;
    int sn = src[e];
    int dn = dst[e];
    float ex   = g_logits[e * HH + h];
    float ssum = g_s[dn * HH + h];
    float gate = g_gates[e * HH + h];
    float w = ex / ssum * gate;
    float4 v4 = *(const float4*)&g_v[(size_t)sn * FF + lane * 4];
    float* aptr = &g_agg[(size_t)dn * FF + lane * 4];
    asm volatile("red.global.add.v4.f32 [%0], {%1,%2,%3,%4};"
                 :: "l"(aptr), "f"(v4.x * w), "f"(v4.y * w),
                    "f"(v4.z * w), "f"(v4.w * w)
                 : "memory");
}

// ---------------- host launcher --------------------------------------------
extern "C" void kernel_launch(void* const* d_in, const int* in_sizes, int n_in,
                              void* d_out, int out_size) {
    const float* feat = (const float*)d_in[0];
    const float* ef   = (const float*)d_in[1];
    const float* Wq   = (const float*)d_in[2];
    const float* Wk   = (const float*)d_in[3];
    const float* Wv   = (const float*)d_in[4];
    const float* Wn   = (const float*)d_in[5];
    const float* Wedge= (const float*)d_in[6];
    const float* Wgate= (const float*)d_in[7];
    const int*   src  = (const int*)d_in[8];
    const int*   dst  = (const int*)d_in[9];
    float* out = (float*)d_out;

    void *qp, *kp, *vp, *aggp;
    cudaGetSymbolAddress(&qp, g_q);
    cudaGetSymbolAddress(&kp, g_k);
    cudaGetSymbolAddress(&vp, g_v);
    cudaGetSymbolAddress(&aggp, g_agg);

    zero_kernel<<<2048, 256>>>();

    const int gm = (NN + 127) / 128;   // 391
    gemm128_xWt<<<gm, 256>>>(feat, Wq, (float*)qp, NN);
    gemm128_xWt<<<gm, 256>>>(feat, Wk, (float*)kp, NN);
    gemm128_xWt<<<gm, 256>>>(feat, Wv, (float*)vp, NN);

    edge_logits_kernel<<<EE / 32, 256>>>(ef, Wedge, Wgate, src, dst);   // 25000 blocks
    edge_exp_kernel<<<(EE * HH) / 256, 256>>>(dst);                     // 25000 blocks
    edge_scatter_kernel<<<(EE * 32) / 256, 256>>>(src, dst);            // 100000 blocks

    gemm128_xWt<<<gm, 256>>>((const float*)aggp, Wn, out, NN);
}

// round 8
// speedup vs baseline: 1.0488x; 1.0488x over previous
#include <cuda_runtime.h>
#include <cuda_bf16.h>
#include <cstdint>
#include <math_constants.h>

// Problem constants
#define NN 50000
#define EE 800000
#define FF 128
#define HH 8
#define DD 16
// logits = (clip(a,-5,5) + bias) / SCALING, SCALING = D^-0.5 = 0.25  => *4

// ---------------- device scratch (static, no runtime alloc) ----------------
__device__ float g_q[(size_t)NN * FF];
__device__ float g_k[(size_t)NN * FF];
__device__ float g_v[(size_t)NN * FF];
__device__ float g_logits[(size_t)EE * HH];   // CSR-ordered (by dst segment)
__device__ float g_gates[(size_t)EE * HH];    // CSR-ordered
__device__ float g_agg[(size_t)NN * FF];
__device__ int   g_cnt[NN];
__device__ int   g_off[NN + 1];
__device__ int   g_cur[NN];
__device__ int   g_pos[EE];       // e -> CSR slot
__device__ int   g_srcperm[EE];   // CSR slot -> src node

// ---------------- CSR build ----------------
__global__ void zero_cnt_kernel() {
    int i = blockIdx.x * blockDim.x + threadIdx.x;
    if (i < NN) g_cnt[i] = 0;
}

__global__ void hist_kernel(const int* __restrict__ dst) {
    int e = blockIdx.x * blockDim.x + threadIdx.x;
    if (e < EE) atomicAdd(&g_cnt[dst[e]], 1);
}

// single-block exclusive scan of g_cnt -> g_off (and g_cur copy)
__global__ void scan_kernel() {
    const int T = 1024;
    __shared__ int sh[T];
    int tid = threadIdx.x;
    const int per = (NN + T - 1) / T;   // 49
    int beg = tid * per;
    int end = beg + per; if (end > NN) end = NN;
    int s = 0;
    for (int i = beg; i < end; i++) s += g_cnt[i];
    sh[tid] = s;
    __syncthreads();
    for (int off = 1; off < T; off <<= 1) {
        int v = (tid >= off) ? sh[tid - off] : 0;
        __syncthreads();
        sh[tid] += v;
        __syncthreads();
    }
    int run = sh[tid] - s;   // exclusive prefix
    for (int i = beg; i < end; i++) {
        g_off[i] = run;
        g_cur[i] = run;
        run += g_cnt[i];
    }
    if (tid == T - 1) g_off[NN] = run;
}

__global__ void fill_kernel(const int* __restrict__ dst,
                            const int* __restrict__ src) {
    int e = blockIdx.x * blockDim.x + threadIdx.x;
    if (e < EE) {
        int p = atomicAdd(&g_cur[dst[e]], 1);
        g_pos[e] = p;
        g_srcperm[p] = src[e];
    }
}

// ---------------- GEMM: C[M,128] = A[M,128] @ W^T ----------------
__device__ __forceinline__ void gemm_body(const float* __restrict__ A,
                                          const float* __restrict__ W,
                                          float* __restrict__ C,
                                          int M, int block_m) {
    __shared__ float As[8][128];
    __shared__ float Bs[8][128];
    const int tid = threadIdx.x;
    const int trow = tid / 16;
    const int tcol = tid % 16;
    const int lr  = tid >> 1;
    const int lc4 = (tid & 1) * 4;
    const bool a_valid = (block_m + lr) < M;

    float acc[8][8];
#pragma unroll
    for (int i = 0; i < 8; i++)
#pragma unroll
        for (int j = 0; j < 8; j++) acc[i][j] = 0.0f;

    for (int k0 = 0; k0 < 128; k0 += 8) {
        float4 a4 = make_float4(0.f, 0.f, 0.f, 0.f);
        if (a_valid)
            a4 = *(const float4*)&A[(size_t)(block_m + lr) * 128 + k0 + lc4];
        float4 b4 = *(const float4*)&W[(size_t)lr * 128 + k0 + lc4];
        As[lc4 + 0][lr] = a4.x; As[lc4 + 1][lr] = a4.y;
        As[lc4 + 2][lr] = a4.z; As[lc4 + 3][lr] = a4.w;
        Bs[lc4 + 0][lr] = b4.x; Bs[lc4 + 1][lr] = b4.y;
        Bs[lc4 + 2][lr] = b4.z; Bs[lc4 + 3][lr] = b4.w;
        __syncthreads();
#pragma unroll
        for (int k = 0; k < 8; k++) {
            float af[8], bf[8];
            *(float4*)&af[0] = *(const float4*)&As[k][trow * 8 + 0];
            *(float4*)&af[4] = *(const float4*)&As[k][trow * 8 + 4];
            *(float4*)&bf[0] = *(const float4*)&Bs[k][tcol * 8 + 0];
            *(float4*)&bf[4] = *(const float4*)&Bs[k][tcol * 8 + 4];
#pragma unroll
            for (int i = 0; i < 8; i++)
#pragma unroll
                for (int j = 0; j < 8; j++) acc[i][j] += af[i] * bf[j];
        }
        __syncthreads();
    }
#pragma unroll
    for (int i = 0; i < 8; i++) {
        int m = block_m + trow * 8 + i;
        if (m < M) {
            *(float4*)&C[(size_t)m * 128 + tcol * 8 + 0] =
                make_float4(acc[i][0], acc[i][1], acc[i][2], acc[i][3]);
            *(float4*)&C[(size_t)m * 128 + tcol * 8 + 4] =
                make_float4(acc[i][4], acc[i][5], acc[i][6], acc[i][7]);
        }
    }
}

// Q, K, V in one grid: blockIdx.y selects which projection.
__global__ void __launch_bounds__(256, 2)
gemm_qkv(const float* __restrict__ A,
         const float* __restrict__ Wq, const float* __restrict__ Wk,
         const float* __restrict__ Wv,
         float* __restrict__ Q, float* __restrict__ K, float* __restrict__ V) {
    const float* W = (blockIdx.y == 0) ? Wq : (blockIdx.y == 1) ? Wk : Wv;
    float*       C = (blockIdx.y == 0) ? Q  : (blockIdx.y == 1) ? K  : V;
    gemm_body(A, W, C, NN, blockIdx.x * 128);
}

__global__ void __launch_bounds__(256, 2)
gemm128_xWt(const float* __restrict__ A, const float* __restrict__ W,
            float* __restrict__ C, int M) {
    gemm_body(A, W, C, M, blockIdx.x * 128);
}

// ---------------- per-edge logits + gates (written CSR-ordered) ------------
// 256 threads = 32 edges x 8 heads per block.
__global__ void __launch_bounds__(256)
edge_logits_kernel(const float* __restrict__ ef,
                   const float* __restrict__ Wedge,
                   const float* __restrict__ Wgate,
                   const int* __restrict__ src,
                   const int* __restrict__ dst) {
    __shared__ float We[HH][FF + 4];
    __shared__ float Wg[HH][FF + 4];
    const int tid = threadIdx.x;
    {
        int h = tid >> 5;
        int c = (tid & 31) * 4;
        *(float4*)&We[h][c] = *(const float4*)&Wedge[h * FF + c];
        *(float4*)&Wg[h][c] = *(const float4*)&Wgate[h * FF + c];
    }
    __syncthreads();

    const int e = blockIdx.x * 32 + (tid >> 3);
    const int h = tid & 7;
    const int sn = src[e];
    const int dn = dst[e];
    const int p  = g_pos[e];       // CSR slot (broadcast across 8 head-threads)

    const float4* qrow = (const float4*)&g_q[(size_t)sn * FF + h * DD];
    const float4* krow = (const float4*)&g_k[(size_t)dn * FF + h * DD];
    float a = 0.0f;
#pragma unroll
    for (int j = 0; j < 4; j++) {
        float4 q4 = qrow[j], k4 = krow[j];
        a += q4.x * k4.x + q4.y * k4.y + q4.z * k4.z + q4.w * k4.w;
    }

    const float4* efrow = (const float4*)&ef[(size_t)e * FF];
    float bias = 0.0f, gdot = 0.0f;
#pragma unroll
    for (int k4 = 0; k4 < 32; k4++) {
        float4 e4 = efrow[k4];
        float4 w4 = *(const float4*)&We[h][k4 * 4];
        float4 g4 = *(const float4*)&Wg[h][k4 * 4];
        bias += e4.x * w4.x + e4.y * w4.y + e4.z * w4.z + e4.w * w4.w;
        gdot += e4.x * g4.x + e4.y * g4.y + e4.z * g4.z + e4.w * g4.w;
    }

    float logit = (fminf(fmaxf(a, -5.0f), 5.0f) + bias) * 4.0f;
    float gate  = 1.0f / (1.0f + expf(-gdot));
    int idx = p * HH + h;          // CSR-ordered store
    g_logits[idx] = logit;
    g_gates[idx]  = gate;
}

// ---------------- node softmax + weighted aggregation (warp per node) ------
// logits/gates/srcperm are CSR-contiguous: fully coalesced passes.
__global__ void __launch_bounds__(256)
node_agg_kernel() {
    int n = (blockIdx.x * blockDim.x + threadIdx.x) >> 5;
    if (n >= NN) return;
    const int lane = threadIdx.x & 31;
    const int beg = g_off[n];
    const int end = g_off[n + 1];

    // pass 1: per-head max (4 edges in parallel, coalesced 128B per step)
    float hmax = -CUDART_INF_F;
    for (int i = beg + (lane >> 3); i < end; i += 4) {
        hmax = fmaxf(hmax, g_logits[i * HH + (lane & 7)]);
    }
    hmax = fmaxf(hmax, __shfl_xor_sync(0xFFFFFFFFu, hmax, 8));
    hmax = fmaxf(hmax, __shfl_xor_sync(0xFFFFFFFFu, hmax, 16));

    // pass 2: per-head sum of exp
    float hsum = 0.0f;
    for (int i = beg + (lane >> 3); i < end; i += 4) {
        hsum += __expf(g_logits[i * HH + (lane & 7)] - hmax);
    }
    hsum += __shfl_xor_sync(0xFFFFFFFFu, hsum, 8);
    hsum += __shfl_xor_sync(0xFFFFFFFFu, hsum, 16);

    // pass 3: weighted aggregation. lane owns head h=lane>>2, cols lane*4..+3
    const int h = lane >> 2;
    float mymax = __shfl_sync(0xFFFFFFFFu, hmax, h);
    float msinv = 1.0f / __shfl_sync(0xFFFFFFFFu, hsum, h);
    float4 acc = make_float4(0.f, 0.f, 0.f, 0.f);
    for (int i = beg; i < end; i++) {
        float w = __expf(g_logits[i * HH + h] - mymax) * msinv
                  * g_gates[i * HH + h];
        float4 v4 = *(const float4*)&g_v[(size_t)g_srcperm[i] * FF + lane * 4];
        acc.x += v4.x * w; acc.y += v4.y * w;
        acc.z += v4.z * w; acc.w += v4.w * w;
    }
    *(float4*)&g_agg[(size_t)n * FF + lane * 4] = acc;
}

// ---------------- host launcher --------------------------------------------
extern "C" void kernel_launch(void* const* d_in, const int* in_sizes, int n_in,
                              void* d_out, int out_size) {
    const float* feat = (const float*)d_in[0];
    const float* ef   = (const float*)d_in[1];
    const float* Wq   = (const float*)d_in[2];
    const float* Wk   = (const float*)d_in[3];
    const float* Wv   = (const float*)d_in[4];
    const float* Wn   = (const float*)d_in[5];
    const float* Wedge= (const float*)d_in[6];
    const float* Wgate= (const float*)d_in[7];
    const int*   src  = (const int*)d_in[8];
    const int*   dst  = (const int*)d_in[9];
    float* out = (float*)d_out;

    void *qp, *kp, *vp, *aggp;
    cudaGetSymbolAddress(&qp, g_q);
    cudaGetSymbolAddress(&kp, g_k);
    cudaGetSymbolAddress(&vp, g_v);
    cudaGetSymbolAddress(&aggp, g_agg);

    // CSR build (cheap int work, runs before the heavy kernels)
    zero_cnt_kernel<<<(NN + 255) / 256, 256>>>();
    hist_kernel<<<(EE + 255) / 256, 256>>>(dst);
    scan_kernel<<<1, 1024>>>();
    fill_kernel<<<(EE + 255) / 256, 256>>>(dst, src);

    const int gm = (NN + 127) / 128;   // 391
    gemm_qkv<<<dim3(gm, 3), 256>>>(feat, Wq, Wk, Wv,
                                   (float*)qp, (float*)kp, (float*)vp);

    edge_logits_kernel<<<EE / 32, 256>>>(ef, Wedge, Wgate, src, dst);
    node_agg_kernel<<<(NN * 32 + 255) / 256, 256>>>();

    gemm128_xWt<<<gm, 256>>>((const float*)aggp, Wn, out, NN);
}